// round 1
// baseline (speedup 1.0000x reference)
#include <cuda_runtime.h>
#include <math.h>

#define E 128
#define H 8
#define L 2048
#define HE 1024
#define HEL (HE * L)
#define NITEMS 50000
#define WAMT 5

// Scratch (device globals; no allocation allowed)
__device__ float g_I[E * L];        // I[e][l]
__device__ float g_QKV[3 * HEL];    // Q,K,V each [h*E+e][l]
__device__ float g_B[HEL];          // attention output b[h*E+e][l]

// ---------------------------------------------------------------------------
// Kernel 1: build I = W_rep[:,cq] + Item[:,sq]; write I_q^T slab + user_init row
// ---------------------------------------------------------------------------
__global__ void build_I_kernel(const int* __restrict__ sq,
                               const int* __restrict__ cq,
                               const float* __restrict__ ir,
                               const float* __restrict__ wr,
                               const float* __restrict__ uir,
                               float* __restrict__ out) {
    int idx = blockIdx.x * blockDim.x + threadIdx.x;   // 0 .. E*L-1, idx = l*128 + e
    if (idx < E) out[idx] = uir[idx];                  // u_state row 0 = user_init
    if (idx >= E * L) return;
    int e = idx & 127;
    int l = idx >> 7;
    float iq = ir[e * NITEMS + sq[l]];
    g_I[e * L + l] = iq + wr[e * WAMT + cq[l]];
    out[E * L + idx] = iq;                             // I_q^T at [262144 + l*128 + e]
}

// ---------------------------------------------------------------------------
// Kernel 2: QKV projection. C(1024x2048) = W(1024x128) @ I(128x2048), z=0,1,2
// ---------------------------------------------------------------------------
__global__ __launch_bounds__(256) void gemm_qkv_kernel(const float* __restrict__ Wq,
                                                       const float* __restrict__ Wk,
                                                       const float* __restrict__ Wv) {
    __shared__ float As[64 * 68];   // As[k][m]
    __shared__ float Bs[64 * 68];   // Bs[k][n]
    const float* W = (blockIdx.z == 0) ? Wq : (blockIdx.z == 1 ? Wk : Wv);
    float* C = g_QKV + (size_t)blockIdx.z * HEL;
    const int bm = blockIdx.y * 64;
    const int bn = blockIdx.x * 64;
    const int t = threadIdx.x, tx = t & 15, ty = t >> 4;

    float acc[4][4];
#pragma unroll
    for (int u = 0; u < 4; u++)
#pragma unroll
        for (int v = 0; v < 4; v++) acc[u][v] = 0.f;

    for (int k0 = 0; k0 < 128; k0 += 64) {
#pragma unroll
        for (int i = t; i < 4096; i += 256) {
            int k = i & 63, m = i >> 6;
            As[k * 68 + m] = W[(bm + m) * 128 + k0 + k];
        }
#pragma unroll
        for (int i = t; i < 4096; i += 256) {
            int n = i & 63, k = i >> 6;
            Bs[k * 68 + n] = g_I[(k0 + k) * L + bn + n];
        }
        __syncthreads();
#pragma unroll 8
        for (int k = 0; k < 64; ++k) {
            float4 a4 = *(const float4*)&As[k * 68 + ty * 4];
            float4 b4 = *(const float4*)&Bs[k * 68 + tx * 4];
            float a[4] = {a4.x, a4.y, a4.z, a4.w};
            float b[4] = {b4.x, b4.y, b4.z, b4.w};
#pragma unroll
            for (int u = 0; u < 4; u++)
#pragma unroll
                for (int v = 0; v < 4; v++) acc[u][v] = fmaf(a[u], b[v], acc[u][v]);
        }
        __syncthreads();
    }
#pragma unroll
    for (int u = 0; u < 4; u++) {
        float4 o4 = {acc[u][0], acc[u][1], acc[u][2], acc[u][3]};
        *(float4*)&C[(size_t)(bm + ty * 4 + u) * L + bn + tx * 4] = o4;
    }
}

// ---------------------------------------------------------------------------
// Kernel 3: flash attention. Per CTA: one head h, one 64-query tile jb.
// score[i,j] = (1/sqrt(E)) * sum_e K[h,e,i] Q[h,e,j], causal i<=j, softmax over i,
// B[h,e,j] = sum_i V[h,e,i] * att[i,j].
// smem: Qs[128][64], KVs[128][64], Ss[64][64], red[64][17], m/l/fac[64]
// ---------------------------------------------------------------------------
#define ATTN_SMEM_FLOATS (8192 + 8192 + 4096 + 64 * 17 + 64 * 3)
#define ATTN_SMEM_BYTES  (ATTN_SMEM_FLOATS * 4)

__global__ __launch_bounds__(256, 2) void attn_kernel() {
    extern __shared__ float sm[];
    float* Qs    = sm;             // [e][jj]  128x64
    float* KVs   = sm + 8192;      // [e][ii]  128x64 (K then V)
    float* Ss    = sm + 16384;     // [ii][jj] 64x64 (p values)
    float* red   = sm + 20480;     // [64][17] partial reductions
    float* m_s   = sm + 21568;     // running max per query col
    float* l_s   = sm + 21632;     // running sum per query col
    float* fac_s = sm + 21696;     // rescale factor per query col

    const int h  = blockIdx.y;
    const int jb = (int)gridDim.x - 1 - (int)blockIdx.x;  // biggest work first
    const int t  = threadIdx.x;
    const int tx = t & 15;
    const int ty = t >> 4;

    const float* Qg = g_QKV + (size_t)(h * E) * L + jb * 64;
    const float* Kg = g_QKV + HEL + (size_t)(h * E) * L;
    const float* Vg = g_QKV + 2 * HEL + (size_t)(h * E) * L;

#pragma unroll
    for (int it = 0; it < 8; ++it) {
        int idx = t + it * 256;
        int e = idx >> 4, c4 = (idx & 15) << 2;
        *(float4*)&Qs[e * 64 + c4] = *(const float4*)&Qg[(size_t)e * L + c4];
    }
    if (t < 64) { m_s[t] = -INFINITY; l_s[t] = 0.0f; }

    float acc[8][4];
#pragma unroll
    for (int u = 0; u < 8; u++)
#pragma unroll
        for (int v = 0; v < 4; v++) acc[u][v] = 0.f;

    const float scale = 0.08838834764831845f;   // 1/sqrt(128)

    for (int ib = 0; ib <= jb; ++ib) {
        __syncthreads();   // S1: prev tile's PV reads done; Q load visible (1st iter)
        const float* Kt = Kg + ib * 64;
        const float* Vt = Vg + ib * 64;
#pragma unroll
        for (int it = 0; it < 8; ++it) {
            int idx = t + it * 256;
            int e = idx >> 4, c4 = (idx & 15) << 2;
            *(float4*)&KVs[e * 64 + c4] = *(const float4*)&Kt[(size_t)e * L + c4];
        }
        __syncthreads();   // S2: K tile ready

        // Phase A: scores s[ii=ty*4+u][jj=tx*4+v]
        float s[4][4];
#pragma unroll
        for (int u = 0; u < 4; u++)
#pragma unroll
            for (int v = 0; v < 4; v++) s[u][v] = 0.f;
#pragma unroll 4
        for (int e = 0; e < 128; ++e) {
            float4 kk = *(const float4*)&KVs[e * 64 + ty * 4];
            float4 qq = *(const float4*)&Qs[e * 64 + tx * 4];
            float ka[4] = {kk.x, kk.y, kk.z, kk.w};
            float qa[4] = {qq.x, qq.y, qq.z, qq.w};
#pragma unroll
            for (int u = 0; u < 4; u++)
#pragma unroll
                for (int v = 0; v < 4; v++) s[u][v] = fmaf(ka[u], qa[v], s[u][v]);
        }
        if (ib == jb) {
#pragma unroll
            for (int u = 0; u < 4; u++)
#pragma unroll
                for (int v = 0; v < 4; v++)
                    s[u][v] = (ty * 4 + u > tx * 4 + v) ? -1e30f : s[u][v] * scale;
        } else {
#pragma unroll
            for (int u = 0; u < 4; u++)
#pragma unroll
                for (int v = 0; v < 4; v++) s[u][v] *= scale;
        }

        // per-column (query) partial max -> red[jj][ty]
#pragma unroll
        for (int v = 0; v < 4; v++) {
            float mx = fmaxf(fmaxf(s[0][v], s[1][v]), fmaxf(s[2][v], s[3][v]));
            red[(tx * 4 + v) * 17 + ty] = mx;
        }
        __syncthreads();   // S3: red ready, K reads finished

        // load V tile (overwrites K) while 64 threads finish the max reduction
#pragma unroll
        for (int it = 0; it < 8; ++it) {
            int idx = t + it * 256;
            int e = idx >> 4, c4 = (idx & 15) << 2;
            *(float4*)&KVs[e * 64 + c4] = *(const float4*)&Vt[(size_t)e * L + c4];
        }
        if (t < 64) {
            float mx = red[t * 17];
#pragma unroll
            for (int y = 1; y < 16; y++) mx = fmaxf(mx, red[t * 17 + y]);
            float mo = m_s[t];
            float mn = fmaxf(mo, mx);
            m_s[t] = mn;
            fac_s[t] = __expf(mo - mn);
        }
        __syncthreads();   // S4: V ready, m/fac ready

        // Phase P: rescale acc, p = exp(s - m), store to Ss, partial column sums
        float mv[4], fv[4], psum[4];
#pragma unroll
        for (int v = 0; v < 4; v++) {
            mv[v] = m_s[tx * 4 + v];
            fv[v] = fac_s[tx * 4 + v];
            psum[v] = 0.f;
        }
#pragma unroll
        for (int u = 0; u < 8; u++)
#pragma unroll
            for (int v = 0; v < 4; v++) acc[u][v] *= fv[v];
#pragma unroll
        for (int u = 0; u < 4; u++) {
            float p0 = __expf(s[u][0] - mv[0]); psum[0] += p0;
            float p1 = __expf(s[u][1] - mv[1]); psum[1] += p1;
            float p2 = __expf(s[u][2] - mv[2]); psum[2] += p2;
            float p3 = __expf(s[u][3] - mv[3]); psum[3] += p3;
            float4 pr = {p0, p1, p2, p3};
            *(float4*)&Ss[(ty * 4 + u) * 64 + tx * 4] = pr;
        }
#pragma unroll
        for (int v = 0; v < 4; v++) red[(tx * 4 + v) * 17 + ty] = psum[v];
        __syncthreads();   // S5: p + partial sums ready

        if (t < 64) {
            float sum = 0.f;
#pragma unroll
            for (int y = 0; y < 16; y++) sum += red[t * 17 + y];
            l_s[t] = l_s[t] * fac_s[t] + sum;
        }

        // Phase B: acc[e=ty*8+u][jj=tx*4+v] += sum_ii V[e][ii] * p[ii][jj]
#pragma unroll 2
        for (int ii = 0; ii < 64; ++ii) {
            float4 p4 = *(const float4*)&Ss[ii * 64 + tx * 4];
            float pa[4] = {p4.x, p4.y, p4.z, p4.w};
#pragma unroll
            for (int u = 0; u < 8; u++) {
                float vv = KVs[(ty * 8 + u) * 64 + ii];
#pragma unroll
                for (int v = 0; v < 4; v++) acc[u][v] = fmaf(vv, pa[v], acc[u][v]);
            }
        }
    }
    __syncthreads();   // l_s final visible to everyone

    float linv[4];
#pragma unroll
    for (int v = 0; v < 4; v++) linv[v] = 1.0f / l_s[tx * 4 + v];
    float* outp = g_B + (size_t)(h * E + ty * 8) * L + jb * 64 + tx * 4;
#pragma unroll
    for (int u = 0; u < 8; u++) {
        float4 o4 = {acc[u][0] * linv[0], acc[u][1] * linv[1],
                     acc[u][2] * linv[2], acc[u][3] * linv[3]};
        *(float4*)&outp[(size_t)u * L] = o4;
    }
}

// ---------------------------------------------------------------------------
// Kernel 4: o = Head_agg(128x1024) @ B(1024x2048), scattered into output layout
// out[128 + j*128 + e] for j<2047, out[524288 + e] for j=2047
// ---------------------------------------------------------------------------
__global__ __launch_bounds__(256) void gemm_out_kernel(const float* __restrict__ A,
                                                       float* __restrict__ out) {
    __shared__ float As[64 * 68];   // As[k][m]
    __shared__ float Bs[64 * 68];   // Bs[k][n]
    const int bm = blockIdx.y * 64;
    const int bn = blockIdx.x * 64;
    const int t = threadIdx.x, tx = t & 15, ty = t >> 4;

    float acc[4][4];
#pragma unroll
    for (int u = 0; u < 4; u++)
#pragma unroll
        for (int v = 0; v < 4; v++) acc[u][v] = 0.f;

    for (int k0 = 0; k0 < 1024; k0 += 64) {
#pragma unroll
        for (int i = t; i < 4096; i += 256) {
            int k = i & 63, m = i >> 6;
            As[k * 68 + m] = A[(bm + m) * 1024 + k0 + k];
        }
#pragma unroll
        for (int i = t; i < 4096; i += 256) {
            int n = i & 63, k = i >> 6;
            Bs[k * 68 + n] = g_B[(size_t)(k0 + k) * L + bn + n];
        }
        __syncthreads();
#pragma unroll 8
        for (int k = 0; k < 64; ++k) {
            float4 a4 = *(const float4*)&As[k * 68 + ty * 4];
            float4 b4 = *(const float4*)&Bs[k * 68 + tx * 4];
            float a[4] = {a4.x, a4.y, a4.z, a4.w};
            float b[4] = {b4.x, b4.y, b4.z, b4.w};
#pragma unroll
            for (int u = 0; u < 4; u++)
#pragma unroll
                for (int v = 0; v < 4; v++) acc[u][v] = fmaf(a[u], b[v], acc[u][v]);
        }
        __syncthreads();
    }
#pragma unroll
    for (int u = 0; u < 4; u++) {
#pragma unroll
        for (int v = 0; v < 4; v++) {
            int e = bm + ty * 4 + u;
            int j = bn + tx * 4 + v;
            int dst = (j < L - 1) ? (E + j * E + e) : (2 * E * L + e);
            out[dst] = acc[u][v];
        }
    }
}

// ---------------------------------------------------------------------------
extern "C" void kernel_launch(void* const* d_in, const int* in_sizes, int n_in,
                              void* d_out, int out_size) {
    const int*   sq   = (const int*)d_in[0];
    const int*   cq   = (const int*)d_in[1];
    const float* ir   = (const float*)d_in[2];
    const float* uir  = (const float*)d_in[3];
    const float* wr   = (const float*)d_in[4];
    const float* Wq   = (const float*)d_in[5];
    const float* Wk   = (const float*)d_in[6];
    const float* Wv   = (const float*)d_in[7];
    const float* Hagg = (const float*)d_in[8];
    float* out = (float*)d_out;

    cudaFuncSetAttribute(attn_kernel, cudaFuncAttributeMaxDynamicSharedMemorySize,
                         ATTN_SMEM_BYTES);

    build_I_kernel<<<(E * L) / 256, 256>>>(sq, cq, ir, wr, uir, out);
    gemm_qkv_kernel<<<dim3(32, 16, 3), 256>>>(Wq, Wk, Wv);
    attn_kernel<<<dim3(32, H), 256, ATTN_SMEM_BYTES>>>();
    gemm_out_kernel<<<dim3(32, 2), 256>>>(Hagg, out);
}

// round 2
// speedup vs baseline: 1.7836x; 1.7836x over previous
#include <cuda_runtime.h>
#include <math.h>

#define E 128
#define H 8
#define L 2048
#define HE 1024
#define HEL (HE * L)
#define NITEMS 50000
#define WAMT 5

// Scratch (device globals; no allocation allowed)
__device__ float g_I[E * L];        // I[e][l]
__device__ float g_QKV[3 * HEL];    // Q,K,V each [h*E+e][l]
__device__ float g_B[HEL];          // attention output b[h*E+e][l]

// ---------------------------------------------------------------------------
// Kernel 1: build I = W_rep[:,cq] + Item[:,sq]; write I_q^T slab + user_init row
// ---------------------------------------------------------------------------
__global__ void build_I_kernel(const int* __restrict__ sq,
                               const int* __restrict__ cq,
                               const float* __restrict__ ir,
                               const float* __restrict__ wr,
                               const float* __restrict__ uir,
                               float* __restrict__ out) {
    int idx = blockIdx.x * blockDim.x + threadIdx.x;   // idx = l*128 + e
    if (idx < E) out[idx] = uir[idx];                  // u_state row 0 = user_init
    if (idx >= E * L) return;
    int e = idx & 127;
    int l = idx >> 7;
    float iq = ir[e * NITEMS + sq[l]];
    g_I[e * L + l] = iq + wr[e * WAMT + cq[l]];
    out[E * L + idx] = iq;                             // I_q^T at [262144 + l*128 + e]
}

// ---------------------------------------------------------------------------
// Kernel 2: QKV projection. C(1024x2048) = W(1024x128) @ I(128x2048), z=0,1,2
// 64x64 tiles, vectorized loads.
// ---------------------------------------------------------------------------
__global__ __launch_bounds__(256) void gemm_qkv_kernel(const float* __restrict__ Wq,
                                                       const float* __restrict__ Wk,
                                                       const float* __restrict__ Wv) {
    __shared__ float As[64 * 68];   // As[k][m]
    __shared__ float Bs[64 * 68];   // Bs[k][n]
    const float* W = (blockIdx.z == 0) ? Wq : (blockIdx.z == 1 ? Wk : Wv);
    float* C = g_QKV + (size_t)blockIdx.z * HEL;
    const int bm = blockIdx.y * 64;
    const int bn = blockIdx.x * 64;
    const int t = threadIdx.x, tx = t & 15, ty = t >> 4;

    float acc[4][4];
#pragma unroll
    for (int u = 0; u < 4; u++)
#pragma unroll
        for (int v = 0; v < 4; v++) acc[u][v] = 0.f;

    for (int k0 = 0; k0 < 128; k0 += 64) {
        // A tile: 64m x 64k, float4 along k, scalar scatter into As[k][m]
#pragma unroll
        for (int r = 0; r < 4; ++r) {
            int id = t + r * 256;
            int m = id >> 4, kq = id & 15;
            float4 w4 = *(const float4*)&W[(bm + m) * 128 + k0 + kq * 4];
            As[(kq * 4 + 0) * 68 + m] = w4.x;
            As[(kq * 4 + 1) * 68 + m] = w4.y;
            As[(kq * 4 + 2) * 68 + m] = w4.z;
            As[(kq * 4 + 3) * 68 + m] = w4.w;
        }
        // B tile: 64k x 64n, float4 along n
#pragma unroll
        for (int r = 0; r < 4; ++r) {
            int id = t + r * 256;
            int k = id >> 4, n4 = (id & 15) << 2;
            *(float4*)&Bs[k * 68 + n4] =
                *(const float4*)&g_I[(size_t)(k0 + k) * L + bn + n4];
        }
        __syncthreads();
#pragma unroll 8
        for (int k = 0; k < 64; ++k) {
            float4 a4 = *(const float4*)&As[k * 68 + ty * 4];
            float4 b4 = *(const float4*)&Bs[k * 68 + tx * 4];
            float a[4] = {a4.x, a4.y, a4.z, a4.w};
            float b[4] = {b4.x, b4.y, b4.z, b4.w};
#pragma unroll
            for (int u = 0; u < 4; u++)
#pragma unroll
                for (int v = 0; v < 4; v++) acc[u][v] = fmaf(a[u], b[v], acc[u][v]);
        }
        __syncthreads();
    }
#pragma unroll
    for (int u = 0; u < 4; u++) {
        float4 o4 = {acc[u][0], acc[u][1], acc[u][2], acc[u][3]};
        *(float4*)&C[(size_t)(bm + ty * 4 + u) * L + bn + tx * 4] = o4;
    }
}

// ---------------------------------------------------------------------------
// Kernel 3: flash attention, causal-balanced. Per CTA: one head h, query tiles
// {31-pid, pid} (work = 33 key-tiles, constant across all 128 CTAs).
// score[i,j] = (1/sqrt(E)) * sum_e K[h,e,i] Q[h,e,j], causal i<=j, softmax over i,
// B[h,e,j] = sum_i V[h,e,i] * att[i,j].
// ---------------------------------------------------------------------------
#define ATTN_SMEM_FLOATS (8192 + 8192 + 4096 + 64 * 17 + 64 * 3)
#define ATTN_SMEM_BYTES  (ATTN_SMEM_FLOATS * 4)

__global__ __launch_bounds__(256, 2) void attn_kernel() {
    extern __shared__ float sm[];
    float* Qs    = sm;             // [e][jj]  128x64
    float* KVs   = sm + 8192;      // [e][ii]  128x64 (K then V)
    float* Ss    = sm + 16384;     // [ii][jj] 64x64 (p values)
    float* red   = sm + 20480;     // [64][17] partial reductions
    float* m_s   = sm + 21568;     // running max per query col
    float* l_s   = sm + 21632;     // running sum per query col
    float* fac_s = sm + 21696;     // rescale factor per query col

    const int h   = blockIdx.y;
    const int pid = blockIdx.x;
    const int t  = threadIdx.x;
    const int tx = t & 15;
    const int ty = t >> 4;

    const float* Kg = g_QKV + HEL + (size_t)(h * E) * L;
    const float* Vg = g_QKV + 2 * HEL + (size_t)(h * E) * L;
    const float scale = 0.08838834764831845f;   // 1/sqrt(128)

#pragma unroll 1
    for (int tt = 0; tt < 2; ++tt) {
        const int jb = tt ? pid : (31 - pid);   // big tile first
        __syncthreads();   // protect m_s/l_s reinit vs prior tile's reads

        const float* Qg = g_QKV + (size_t)(h * E) * L + jb * 64;
#pragma unroll
        for (int it = 0; it < 8; ++it) {
            int idx = t + it * 256;
            int e = idx >> 4, c4 = (idx & 15) << 2;
            *(float4*)&Qs[e * 64 + c4] = *(const float4*)&Qg[(size_t)e * L + c4];
        }
        if (t < 64) { m_s[t] = -INFINITY; l_s[t] = 0.0f; }

        float acc[8][4];
#pragma unroll
        for (int u = 0; u < 8; u++)
#pragma unroll
            for (int v = 0; v < 4; v++) acc[u][v] = 0.f;

        for (int ib = 0; ib <= jb; ++ib) {
            __syncthreads();   // S1: prev PV reads done; Q/init visible on first iter
            const float* Kt = Kg + ib * 64;
            const float* Vt = Vg + ib * 64;
#pragma unroll
            for (int it = 0; it < 8; ++it) {
                int idx = t + it * 256;
                int e = idx >> 4, c4 = (idx & 15) << 2;
                *(float4*)&KVs[e * 64 + c4] = *(const float4*)&Kt[(size_t)e * L + c4];
            }
            __syncthreads();   // S2: K tile ready

            // Phase A: scores s[ii=ty*4+u][jj=tx*4+v]
            float s[4][4];
#pragma unroll
            for (int u = 0; u < 4; u++)
#pragma unroll
                for (int v = 0; v < 4; v++) s[u][v] = 0.f;
#pragma unroll 4
            for (int e = 0; e < 128; ++e) {
                float4 kk = *(const float4*)&KVs[e * 64 + ty * 4];
                float4 qq = *(const float4*)&Qs[e * 64 + tx * 4];
                float ka[4] = {kk.x, kk.y, kk.z, kk.w};
                float qa[4] = {qq.x, qq.y, qq.z, qq.w};
#pragma unroll
                for (int u = 0; u < 4; u++)
#pragma unroll
                    for (int v = 0; v < 4; v++) s[u][v] = fmaf(ka[u], qa[v], s[u][v]);
            }
            if (ib == jb) {
#pragma unroll
                for (int u = 0; u < 4; u++)
#pragma unroll
                    for (int v = 0; v < 4; v++)
                        s[u][v] = (ty * 4 + u > tx * 4 + v) ? -1e30f : s[u][v] * scale;
            } else {
#pragma unroll
                for (int u = 0; u < 4; u++)
#pragma unroll
                    for (int v = 0; v < 4; v++) s[u][v] *= scale;
            }

            // per-column (query) partial max -> red[jj][ty]
#pragma unroll
            for (int v = 0; v < 4; v++) {
                float mx = fmaxf(fmaxf(s[0][v], s[1][v]), fmaxf(s[2][v], s[3][v]));
                red[(tx * 4 + v) * 17 + ty] = mx;
            }
            __syncthreads();   // S3: red ready, K reads finished

            // load V tile (overwrites K) while 64 threads finish the max reduction
#pragma unroll
            for (int it = 0; it < 8; ++it) {
                int idx = t + it * 256;
                int e = idx >> 4, c4 = (idx & 15) << 2;
                *(float4*)&KVs[e * 64 + c4] = *(const float4*)&Vt[(size_t)e * L + c4];
            }
            if (t < 64) {
                float mx = red[t * 17];
#pragma unroll
                for (int y = 1; y < 16; y++) mx = fmaxf(mx, red[t * 17 + y]);
                float mo = m_s[t];
                float mn = fmaxf(mo, mx);
                m_s[t] = mn;
                fac_s[t] = __expf(mo - mn);
            }
            __syncthreads();   // S4: V ready, m/fac ready

            // Phase P: rescale acc, p = exp(s - m), store to Ss, partial sums
            float mv[4], fv[4], psum[4];
#pragma unroll
            for (int v = 0; v < 4; v++) {
                mv[v] = m_s[tx * 4 + v];
                fv[v] = fac_s[tx * 4 + v];
                psum[v] = 0.f;
            }
#pragma unroll
            for (int u = 0; u < 8; u++)
#pragma unroll
                for (int v = 0; v < 4; v++) acc[u][v] *= fv[v];
#pragma unroll
            for (int u = 0; u < 4; u++) {
                float p0 = __expf(s[u][0] - mv[0]); psum[0] += p0;
                float p1 = __expf(s[u][1] - mv[1]); psum[1] += p1;
                float p2 = __expf(s[u][2] - mv[2]); psum[2] += p2;
                float p3 = __expf(s[u][3] - mv[3]); psum[3] += p3;
                float4 pr = {p0, p1, p2, p3};
                *(float4*)&Ss[(ty * 4 + u) * 64 + tx * 4] = pr;
            }
#pragma unroll
            for (int v = 0; v < 4; v++) red[(tx * 4 + v) * 17 + ty] = psum[v];
            __syncthreads();   // S5: p + partial sums ready

            if (t < 64) {
                float sum = 0.f;
#pragma unroll
                for (int y = 0; y < 16; y++) sum += red[t * 17 + y];
                l_s[t] = l_s[t] * fac_s[t] + sum;
            }

            // Phase B (vectorized): acc[e=ty*8+u][jj=tx*4+v] += sum_ii V[e][ii]*p[ii][jj]
#pragma unroll 2
            for (int ii0 = 0; ii0 < 64; ii0 += 4) {
                float4 p0 = *(const float4*)&Ss[(ii0 + 0) * 64 + tx * 4];
                float4 p1 = *(const float4*)&Ss[(ii0 + 1) * 64 + tx * 4];
                float4 p2 = *(const float4*)&Ss[(ii0 + 2) * 64 + tx * 4];
                float4 p3 = *(const float4*)&Ss[(ii0 + 3) * 64 + tx * 4];
#pragma unroll
                for (int u = 0; u < 8; u++) {
                    float4 v4 = *(const float4*)&KVs[(ty * 8 + u) * 64 + ii0];
                    acc[u][0] = fmaf(v4.x, p0.x, acc[u][0]);
                    acc[u][1] = fmaf(v4.x, p0.y, acc[u][1]);
                    acc[u][2] = fmaf(v4.x, p0.z, acc[u][2]);
                    acc[u][3] = fmaf(v4.x, p0.w, acc[u][3]);
                    acc[u][0] = fmaf(v4.y, p1.x, acc[u][0]);
                    acc[u][1] = fmaf(v4.y, p1.y, acc[u][1]);
                    acc[u][2] = fmaf(v4.y, p1.z, acc[u][2]);
                    acc[u][3] = fmaf(v4.y, p1.w, acc[u][3]);
                    acc[u][0] = fmaf(v4.z, p2.x, acc[u][0]);
                    acc[u][1] = fmaf(v4.z, p2.y, acc[u][1]);
                    acc[u][2] = fmaf(v4.z, p2.z, acc[u][2]);
                    acc[u][3] = fmaf(v4.z, p2.w, acc[u][3]);
                    acc[u][0] = fmaf(v4.w, p3.x, acc[u][0]);
                    acc[u][1] = fmaf(v4.w, p3.y, acc[u][1]);
                    acc[u][2] = fmaf(v4.w, p3.z, acc[u][2]);
                    acc[u][3] = fmaf(v4.w, p3.w, acc[u][3]);
                }
            }
        }
        __syncthreads();   // l_s final visible to everyone

        float linv[4];
#pragma unroll
        for (int v = 0; v < 4; v++) linv[v] = 1.0f / l_s[tx * 4 + v];
        float* outp = g_B + (size_t)(h * E + ty * 8) * L + jb * 64 + tx * 4;
#pragma unroll
        for (int u = 0; u < 8; u++) {
            float4 o4 = {acc[u][0] * linv[0], acc[u][1] * linv[1],
                         acc[u][2] * linv[2], acc[u][3] * linv[3]};
            *(float4*)&outp[(size_t)u * L] = o4;
        }
    }
}

// ---------------------------------------------------------------------------
// Kernel 4: o = Head_agg(128x1024) @ B(1024x2048), scattered into output layout
// 64x32 tiles -> 128 CTAs, float4 loads. out[128+j*128+e] (j<2047), out[524288+e]
// ---------------------------------------------------------------------------
__global__ __launch_bounds__(256) void gemm_out_kernel(const float* __restrict__ A,
                                                       float* __restrict__ out) {
    __shared__ float As[64 * 66];   // As[k][m], 64k x 64m
    __shared__ float Bs[64 * 36];   // Bs[k][n], 64k x 32n
    const int bm = blockIdx.y * 64;
    const int bn = blockIdx.x * 32;
    const int t = threadIdx.x, tx = t & 7, ty = t >> 3;   // ty: 0..31

    float acc[2][4];
#pragma unroll
    for (int u = 0; u < 2; u++)
#pragma unroll
        for (int v = 0; v < 4; v++) acc[u][v] = 0.f;

    for (int k0 = 0; k0 < 1024; k0 += 64) {
        // A tile: 64m x 64k, float4 along k
#pragma unroll
        for (int r = 0; r < 4; ++r) {
            int id = t + r * 256;
            int m = id >> 4, kq = id & 15;
            float4 a4 = *(const float4*)&A[(bm + m) * 1024 + k0 + kq * 4];
            As[(kq * 4 + 0) * 66 + m] = a4.x;
            As[(kq * 4 + 1) * 66 + m] = a4.y;
            As[(kq * 4 + 2) * 66 + m] = a4.z;
            As[(kq * 4 + 3) * 66 + m] = a4.w;
        }
        // B tile: 64k x 32n, float4 along n
#pragma unroll
        for (int r = 0; r < 2; ++r) {
            int id = t + r * 256;
            int k = id >> 3, n4 = (id & 7) << 2;
            *(float4*)&Bs[k * 36 + n4] =
                *(const float4*)&g_B[(size_t)(k0 + k) * L + bn + n4];
        }
        __syncthreads();
#pragma unroll 8
        for (int k = 0; k < 64; ++k) {
            float2 a2 = *(const float2*)&As[k * 66 + ty * 2];
            float4 b4 = *(const float4*)&Bs[k * 36 + tx * 4];
            acc[0][0] = fmaf(a2.x, b4.x, acc[0][0]);
            acc[0][1] = fmaf(a2.x, b4.y, acc[0][1]);
            acc[0][2] = fmaf(a2.x, b4.z, acc[0][2]);
            acc[0][3] = fmaf(a2.x, b4.w, acc[0][3]);
            acc[1][0] = fmaf(a2.y, b4.x, acc[1][0]);
            acc[1][1] = fmaf(a2.y, b4.y, acc[1][1]);
            acc[1][2] = fmaf(a2.y, b4.z, acc[1][2]);
            acc[1][3] = fmaf(a2.y, b4.w, acc[1][3]);
        }
        __syncthreads();
    }
#pragma unroll
    for (int u = 0; u < 2; u++) {
#pragma unroll
        for (int v = 0; v < 4; v++) {
            int e = bm + ty * 2 + u;
            int j = bn + tx * 4 + v;
            int dst = (j < L - 1) ? (E + j * E + e) : (2 * E * L + e);
            out[dst] = acc[u][v];
        }
    }
}

// ---------------------------------------------------------------------------
extern "C" void kernel_launch(void* const* d_in, const int* in_sizes, int n_in,
                              void* d_out, int out_size) {
    const int*   sq   = (const int*)d_in[0];
    const int*   cq   = (const int*)d_in[1];
    const float* ir   = (const float*)d_in[2];
    const float* uir  = (const float*)d_in[3];
    const float* wr   = (const float*)d_in[4];
    const float* Wq   = (const float*)d_in[5];
    const float* Wk   = (const float*)d_in[6];
    const float* Wv   = (const float*)d_in[7];
    const float* Hagg = (const float*)d_in[8];
    float* out = (float*)d_out;

    cudaFuncSetAttribute(attn_kernel, cudaFuncAttributeMaxDynamicSharedMemorySize,
                         ATTN_SMEM_BYTES);

    build_I_kernel<<<(E * L) / 256, 256>>>(sq, cq, ir, wr, uir, out);
    gemm_qkv_kernel<<<dim3(32, 16, 3), 256>>>(Wq, Wk, Wv);
    attn_kernel<<<dim3(16, H), 256, ATTN_SMEM_BYTES>>>();
    gemm_out_kernel<<<dim3(64, 2), 256>>>(Hagg, out);
}

// round 3
// speedup vs baseline: 1.7855x; 1.0010x over previous
#include <cuda_runtime.h>
#include <math.h>

#define E 128
#define H 8
#define L 2048
#define HE 1024
#define HEL (HE * L)
#define NITEMS 50000
#define WAMT 5

// Scratch (device globals; no allocation allowed)
__device__ float g_I[E * L];        // I[e][l]
__device__ float g_QKV[3 * HEL];    // Q,K,V each [h*E+e][l]
__device__ float g_B[HEL];          // attention output b[h*E+e][l]

// ---------------------------------------------------------------------------
// Kernel 1: build I = W_rep[:,cq] + Item[:,sq]; write I_q^T slab + user_init row
// ---------------------------------------------------------------------------
__global__ void build_I_kernel(const int* __restrict__ sq,
                               const int* __restrict__ cq,
                               const float* __restrict__ ir,
                               const float* __restrict__ wr,
                               const float* __restrict__ uir,
                               float* __restrict__ out) {
    int idx = blockIdx.x * blockDim.x + threadIdx.x;   // idx = l*128 + e
    if (idx < E) out[idx] = uir[idx];                  // u_state row 0 = user_init
    if (idx >= E * L) return;
    int e = idx & 127;
    int l = idx >> 7;
    float iq = ir[e * NITEMS + sq[l]];
    g_I[e * L + l] = iq + wr[e * WAMT + cq[l]];
    out[E * L + idx] = iq;                             // I_q^T at [262144 + l*128 + e]
}

// ---------------------------------------------------------------------------
// Kernel 2: QKV projection. C(1024x2048) = W(1024x128) @ I(128x2048), z=0,1,2
// 64x64 tiles, vectorized loads.
// ---------------------------------------------------------------------------
__global__ __launch_bounds__(256) void gemm_qkv_kernel(const float* __restrict__ Wq,
                                                       const float* __restrict__ Wk,
                                                       const float* __restrict__ Wv) {
    __shared__ float As[64 * 68];   // As[k][m]
    __shared__ float Bs[64 * 68];   // Bs[k][n]
    const float* W = (blockIdx.z == 0) ? Wq : (blockIdx.z == 1 ? Wk : Wv);
    float* C = g_QKV + (size_t)blockIdx.z * HEL;
    const int bm = blockIdx.y * 64;
    const int bn = blockIdx.x * 64;
    const int t = threadIdx.x, tx = t & 15, ty = t >> 4;

    float acc[4][4];
#pragma unroll
    for (int u = 0; u < 4; u++)
#pragma unroll
        for (int v = 0; v < 4; v++) acc[u][v] = 0.f;

    for (int k0 = 0; k0 < 128; k0 += 64) {
        // A tile: 64m x 64k, float4 along k, scalar scatter into As[k][m]
#pragma unroll
        for (int r = 0; r < 4; ++r) {
            int id = t + r * 256;
            int m = id >> 4, kq = id & 15;
            float4 w4 = *(const float4*)&W[(bm + m) * 128 + k0 + kq * 4];
            As[(kq * 4 + 0) * 68 + m] = w4.x;
            As[(kq * 4 + 1) * 68 + m] = w4.y;
            As[(kq * 4 + 2) * 68 + m] = w4.z;
            As[(kq * 4 + 3) * 68 + m] = w4.w;
        }
        // B tile: 64k x 64n, float4 along n
#pragma unroll
        for (int r = 0; r < 4; ++r) {
            int id = t + r * 256;
            int k = id >> 4, n4 = (id & 15) << 2;
            *(float4*)&Bs[k * 68 + n4] =
                *(const float4*)&g_I[(size_t)(k0 + k) * L + bn + n4];
        }
        __syncthreads();
#pragma unroll 8
        for (int k = 0; k < 64; ++k) {
            float4 a4 = *(const float4*)&As[k * 68 + ty * 4];
            float4 b4 = *(const float4*)&Bs[k * 68 + tx * 4];
            float a[4] = {a4.x, a4.y, a4.z, a4.w};
            float b[4] = {b4.x, b4.y, b4.z, b4.w};
#pragma unroll
            for (int u = 0; u < 4; u++)
#pragma unroll
                for (int v = 0; v < 4; v++) acc[u][v] = fmaf(a[u], b[v], acc[u][v]);
        }
        __syncthreads();
    }
#pragma unroll
    for (int u = 0; u < 4; u++) {
        float4 o4 = {acc[u][0], acc[u][1], acc[u][2], acc[u][3]};
        *(float4*)&C[(size_t)(bm + ty * 4 + u) * L + bn + tx * 4] = o4;
    }
}

// ---------------------------------------------------------------------------
// Kernel 3: flash attention, causal-balanced. Per CTA: one head h, query tiles
// {31-pid, pid} (work = 33 key-tiles, constant across all 128 CTAs).
// score[i,j] = (1/sqrt(E)) * sum_e K[h,e,i] Q[h,e,j], causal i<=j, softmax over i,
// B[h,e,j] = sum_i V[h,e,i] * att[i,j].
// ---------------------------------------------------------------------------
#define ATTN_SMEM_FLOATS (8192 + 8192 + 4096 + 64 * 17 + 64 * 3)
#define ATTN_SMEM_BYTES  (ATTN_SMEM_FLOATS * 4)

__global__ __launch_bounds__(256, 2) void attn_kernel() {
    extern __shared__ float sm[];
    float* Qs    = sm;             // [e][jj]  128x64
    float* KVs   = sm + 8192;      // [e][ii]  128x64 (K then V)
    float* Ss    = sm + 16384;     // [ii][jj] 64x64 (p values)
    float* red   = sm + 20480;     // [64][17] partial reductions
    float* m_s   = sm + 21568;     // running max per query col
    float* l_s   = sm + 21632;     // running sum per query col
    float* fac_s = sm + 21696;     // rescale factor per query col

    const int h   = blockIdx.y;
    const int pid = blockIdx.x;
    const int t  = threadIdx.x;
    const int tx = t & 15;
    const int ty = t >> 4;

    const float* Kg = g_QKV + HEL + (size_t)(h * E) * L;
    const float* Vg = g_QKV + 2 * HEL + (size_t)(h * E) * L;
    const float scale = 0.08838834764831845f;   // 1/sqrt(128)

#pragma unroll 1
    for (int tt = 0; tt < 2; ++tt) {
        const int jb = tt ? pid : (31 - pid);   // big tile first
        __syncthreads();   // protect m_s/l_s reinit vs prior tile's reads

        const float* Qg = g_QKV + (size_t)(h * E) * L + jb * 64;
#pragma unroll
        for (int it = 0; it < 8; ++it) {
            int idx = t + it * 256;
            int e = idx >> 4, c4 = (idx & 15) << 2;
            *(float4*)&Qs[e * 64 + c4] = *(const float4*)&Qg[(size_t)e * L + c4];
        }
        if (t < 64) { m_s[t] = -INFINITY; l_s[t] = 0.0f; }

        float acc[8][4];
#pragma unroll
        for (int u = 0; u < 8; u++)
#pragma unroll
            for (int v = 0; v < 4; v++) acc[u][v] = 0.f;

        for (int ib = 0; ib <= jb; ++ib) {
            __syncthreads();   // S1: prev PV reads done; Q/init visible on first iter
            const float* Kt = Kg + ib * 64;
            const float* Vt = Vg + ib * 64;
#pragma unroll
            for (int it = 0; it < 8; ++it) {
                int idx = t + it * 256;
                int e = idx >> 4, c4 = (idx & 15) << 2;
                *(float4*)&KVs[e * 64 + c4] = *(const float4*)&Kt[(size_t)e * L + c4];
            }
            __syncthreads();   // S2: K tile ready

            // Phase A: scores s[ii=ty*4+u][jj=tx*4+v]
            float s[4][4];
#pragma unroll
            for (int u = 0; u < 4; u++)
#pragma unroll
                for (int v = 0; v < 4; v++) s[u][v] = 0.f;
#pragma unroll 4
            for (int e = 0; e < 128; ++e) {
                float4 kk = *(const float4*)&KVs[e * 64 + ty * 4];
                float4 qq = *(const float4*)&Qs[e * 64 + tx * 4];
                float ka[4] = {kk.x, kk.y, kk.z, kk.w};
                float qa[4] = {qq.x, qq.y, qq.z, qq.w};
#pragma unroll
                for (int u = 0; u < 4; u++)
#pragma unroll
                    for (int v = 0; v < 4; v++) s[u][v] = fmaf(ka[u], qa[v], s[u][v]);
            }
            if (ib == jb) {
#pragma unroll
                for (int u = 0; u < 4; u++)
#pragma unroll
                    for (int v = 0; v < 4; v++)
                        s[u][v] = (ty * 4 + u > tx * 4 + v) ? -1e30f : s[u][v] * scale;
            } else {
#pragma unroll
                for (int u = 0; u < 4; u++)
#pragma unroll
                    for (int v = 0; v < 4; v++) s[u][v] *= scale;
            }

            // per-column (query) partial max -> red[jj][ty]
#pragma unroll
            for (int v = 0; v < 4; v++) {
                float mx = fmaxf(fmaxf(s[0][v], s[1][v]), fmaxf(s[2][v], s[3][v]));
                red[(tx * 4 + v) * 17 + ty] = mx;
            }
            __syncthreads();   // S3: red ready, K reads finished

            // load V tile (overwrites K) while 64 threads finish the max reduction
#pragma unroll
            for (int it = 0; it < 8; ++it) {
                int idx = t + it * 256;
                int e = idx >> 4, c4 = (idx & 15) << 2;
                *(float4*)&KVs[e * 64 + c4] = *(const float4*)&Vt[(size_t)e * L + c4];
            }
            if (t < 64) {
                float mx = red[t * 17];
#pragma unroll
                for (int y = 1; y < 16; y++) mx = fmaxf(mx, red[t * 17 + y]);
                float mo = m_s[t];
                float mn = fmaxf(mo, mx);
                m_s[t] = mn;
                fac_s[t] = __expf(mo - mn);
            }
            __syncthreads();   // S4: V ready, m/fac ready

            // Phase P: rescale acc, p = exp(s - m), store to Ss, partial sums
            float mv[4], fv[4], psum[4];
#pragma unroll
            for (int v = 0; v < 4; v++) {
                mv[v] = m_s[tx * 4 + v];
                fv[v] = fac_s[tx * 4 + v];
                psum[v] = 0.f;
            }
#pragma unroll
            for (int u = 0; u < 8; u++)
#pragma unroll
                for (int v = 0; v < 4; v++) acc[u][v] *= fv[v];
#pragma unroll
            for (int u = 0; u < 4; u++) {
                float p0 = __expf(s[u][0] - mv[0]); psum[0] += p0;
                float p1 = __expf(s[u][1] - mv[1]); psum[1] += p1;
                float p2 = __expf(s[u][2] - mv[2]); psum[2] += p2;
                float p3 = __expf(s[u][3] - mv[3]); psum[3] += p3;
                float4 pr = {p0, p1, p2, p3};
                *(float4*)&Ss[(ty * 4 + u) * 64 + tx * 4] = pr;
            }
#pragma unroll
            for (int v = 0; v < 4; v++) red[(tx * 4 + v) * 17 + ty] = psum[v];
            __syncthreads();   // S5: p + partial sums ready

            if (t < 64) {
                float sum = 0.f;
#pragma unroll
                for (int y = 0; y < 16; y++) sum += red[t * 17 + y];
                l_s[t] = l_s[t] * fac_s[t] + sum;
            }

            // Phase B (vectorized): acc[e=ty*8+u][jj=tx*4+v] += sum_ii V[e][ii]*p[ii][jj]
#pragma unroll 2
            for (int ii0 = 0; ii0 < 64; ii0 += 4) {
                float4 p0 = *(const float4*)&Ss[(ii0 + 0) * 64 + tx * 4];
                float4 p1 = *(const float4*)&Ss[(ii0 + 1) * 64 + tx * 4];
                float4 p2 = *(const float4*)&Ss[(ii0 + 2) * 64 + tx * 4];
                float4 p3 = *(const float4*)&Ss[(ii0 + 3) * 64 + tx * 4];
#pragma unroll
                for (int u = 0; u < 8; u++) {
                    float4 v4 = *(const float4*)&KVs[(ty * 8 + u) * 64 + ii0];
                    acc[u][0] = fmaf(v4.x, p0.x, acc[u][0]);
                    acc[u][1] = fmaf(v4.x, p0.y, acc[u][1]);
                    acc[u][2] = fmaf(v4.x, p0.z, acc[u][2]);
                    acc[u][3] = fmaf(v4.x, p0.w, acc[u][3]);
                    acc[u][0] = fmaf(v4.y, p1.x, acc[u][0]);
                    acc[u][1] = fmaf(v4.y, p1.y, acc[u][1]);
                    acc[u][2] = fmaf(v4.y, p1.z, acc[u][2]);
                    acc[u][3] = fmaf(v4.y, p1.w, acc[u][3]);
                    acc[u][0] = fmaf(v4.z, p2.x, acc[u][0]);
                    acc[u][1] = fmaf(v4.z, p2.y, acc[u][1]);
                    acc[u][2] = fmaf(v4.z, p2.z, acc[u][2]);
                    acc[u][3] = fmaf(v4.z, p2.w, acc[u][3]);
                    acc[u][0] = fmaf(v4.w, p3.x, acc[u][0]);
                    acc[u][1] = fmaf(v4.w, p3.y, acc[u][1]);
                    acc[u][2] = fmaf(v4.w, p3.z, acc[u][2]);
                    acc[u][3] = fmaf(v4.w, p3.w, acc[u][3]);
                }
            }
        }
        __syncthreads();   // l_s final visible to everyone

        float linv[4];
#pragma unroll
        for (int v = 0; v < 4; v++) linv[v] = 1.0f / l_s[tx * 4 + v];
        float* outp = g_B + (size_t)(h * E + ty * 8) * L + jb * 64 + tx * 4;
#pragma unroll
        for (int u = 0; u < 8; u++) {
            float4 o4 = {acc[u][0] * linv[0], acc[u][1] * linv[1],
                         acc[u][2] * linv[2], acc[u][3] * linv[3]};
            *(float4*)&outp[(size_t)u * L] = o4;
        }
    }
}

// ---------------------------------------------------------------------------
// Kernel 4: o = Head_agg(128x1024) @ B(1024x2048), scattered into output layout
// 64x32 tiles -> 128 CTAs, float4 loads. out[128+j*128+e] (j<2047), out[524288+e]
// ---------------------------------------------------------------------------
__global__ __launch_bounds__(256) void gemm_out_kernel(const float* __restrict__ A,
                                                       float* __restrict__ out) {
    __shared__ float As[64 * 66];   // As[k][m], 64k x 64m
    __shared__ float Bs[64 * 36];   // Bs[k][n], 64k x 32n
    const int bm = blockIdx.y * 64;
    const int bn = blockIdx.x * 32;
    const int t = threadIdx.x, tx = t & 7, ty = t >> 3;   // ty: 0..31

    float acc[2][4];
#pragma unroll
    for (int u = 0; u < 2; u++)
#pragma unroll
        for (int v = 0; v < 4; v++) acc[u][v] = 0.f;

    for (int k0 = 0; k0 < 1024; k0 += 64) {
        // A tile: 64m x 64k, float4 along k
#pragma unroll
        for (int r = 0; r < 4; ++r) {
            int id = t + r * 256;
            int m = id >> 4, kq = id & 15;
            float4 a4 = *(const float4*)&A[(bm + m) * 1024 + k0 + kq * 4];
            As[(kq * 4 + 0) * 66 + m] = a4.x;
            As[(kq * 4 + 1) * 66 + m] = a4.y;
            As[(kq * 4 + 2) * 66 + m] = a4.z;
            As[(kq * 4 + 3) * 66 + m] = a4.w;
        }
        // B tile: 64k x 32n, float4 along n
#pragma unroll
        for (int r = 0; r < 2; ++r) {
            int id = t + r * 256;
            int k = id >> 3, n4 = (id & 7) << 2;
            *(float4*)&Bs[k * 36 + n4] =
                *(const float4*)&g_B[(size_t)(k0 + k) * L + bn + n4];
        }
        __syncthreads();
#pragma unroll 8
        for (int k = 0; k < 64; ++k) {
            float2 a2 = *(const float2*)&As[k * 66 + ty * 2];
            float4 b4 = *(const float4*)&Bs[k * 36 + tx * 4];
            acc[0][0] = fmaf(a2.x, b4.x, acc[0][0]);
            acc[0][1] = fmaf(a2.x, b4.y, acc[0][1]);
            acc[0][2] = fmaf(a2.x, b4.z, acc[0][2]);
            acc[0][3] = fmaf(a2.x, b4.w, acc[0][3]);
            acc[1][0] = fmaf(a2.y, b4.x, acc[1][0]);
            acc[1][1] = fmaf(a2.y, b4.y, acc[1][1]);
            acc[1][2] = fmaf(a2.y, b4.z, acc[1][2]);
            acc[1][3] = fmaf(a2.y, b4.w, acc[1][3]);
        }
        __syncthreads();
    }
#pragma unroll
    for (int u = 0; u < 2; u++) {
#pragma unroll
        for (int v = 0; v < 4; v++) {
            int e = bm + ty * 2 + u;
            int j = bn + tx * 4 + v;
            int dst = (j < L - 1) ? (E + j * E + e) : (2 * E * L + e);
            out[dst] = acc[u][v];
        }
    }
}

// ---------------------------------------------------------------------------
extern "C" void kernel_launch(void* const* d_in, const int* in_sizes, int n_in,
                              void* d_out, int out_size) {
    const int*   sq   = (const int*)d_in[0];
    const int*   cq   = (const int*)d_in[1];
    const float* ir   = (const float*)d_in[2];
    const float* uir  = (const float*)d_in[3];
    const float* wr   = (const float*)d_in[4];
    const float* Wq   = (const float*)d_in[5];
    const float* Wk   = (const float*)d_in[6];
    const float* Wv   = (const float*)d_in[7];
    const float* Hagg = (const float*)d_in[8];
    float* out = (float*)d_out;

    cudaFuncSetAttribute(attn_kernel, cudaFuncAttributeMaxDynamicSharedMemorySize,
                         ATTN_SMEM_BYTES);

    build_I_kernel<<<(E * L) / 256, 256>>>(sq, cq, ir, wr, uir, out);
    gemm_qkv_kernel<<<dim3(32, 16, 3), 256>>>(Wq, Wk, Wv);
    attn_kernel<<<dim3(16, H), 256, ATTN_SMEM_BYTES>>>();
    gemm_out_kernel<<<dim3(64, 2), 256>>>(Hagg, out);
}